// round 15
// baseline (speedup 1.0000x reference)
#include <cuda_runtime.h>
#include <cuda_bf16.h>
#include <math.h>
#include <stdint.h>

#define BB 64
#define TT 2048
#define DIM 256
#define VOCAB 32000
#define TAILF 96
#define EPS_CUT 1e-7f

__device__ float d_hT[BB * DIM];   // [b][k] fp32

// packed f32x2 FMA: c = a*b + c (elementwise on 2 packed fp32)
#define FMA2(c, a, b) \
    asm("fma.rn.f32x2 %0, %1, %2, %0;" : "+l"(c) : "l"(a), "l"(b))
__device__ __forceinline__ float2 unpack2(unsigned long long v) {
    float2 r;
    asm("mov.b64 {%0,%1}, %2;" : "=f"(r.x), "=f"(r.y) : "l"(v));
    return r;
}
__device__ __forceinline__ unsigned long long dup2(float s) {
    unsigned long long d;
    asm("mov.b64 %0, {%1,%1};" : "=l"(d) : "f"(s));
    return d;
}

// ---------------------------------------------------------------------------
// K1 (fused scan+main). P4 now 2-way t-unrolled: two independent FMA/tanh
// streams per iteration (separate accumulators) to double ILP on the
// serial LDS->FMA-chain->shuffle->tanh path.
// ---------------------------------------------------------------------------
#define RQP 68
#define ROWS 272
#define DSMEM_F (TAILF * ROWS * 4)

#define RNN_STEP(slot, accv) do {                                          \
    const ulonglong2* ev =                                                 \
        (const ulonglong2*)&e_s[(slot) * ROWS + kq * RQP];                 \
    unsigned long long a0 = 0, a1 = 0, a2 = 0, a3 = 0;                     \
    _Pragma("unroll")                                                      \
    for (int j = 0; j < 16; j += 2) {                                      \
        ulonglong2 e0 = ev[j];                                             \
        FMA2(a0, wp[2 * j], e0.x);                                         \
        FMA2(a1, wp[2 * j + 1], e0.y);                                     \
        ulonglong2 e1 = ev[j + 1];                                         \
        FMA2(a2, wp[2 * j + 2], e1.x);                                     \
        FMA2(a3, wp[2 * j + 3], e1.y);                                     \
    }                                                                      \
    float2 f0 = unpack2(a0), f1 = unpack2(a1);                             \
    float2 f2 = unpack2(a2), f3 = unpack2(a3);                             \
    float ps = ((f0.x + f0.y) + (f1.x + f1.y)) +                           \
               ((f2.x + f2.y) + (f3.x + f3.y));                            \
    ps += __shfl_xor_sync(0xffffffffu, ps, 1);                             \
    ps += __shfl_xor_sync(0xffffffffu, ps, 2);                             \
    accv = fmaf(w_sh[slot], tanhf(ps + wb), accv);                         \
} while (0)

__global__ void __launch_bounds__(512, 1) k_fused(
        const int* __restrict__ x, const float* __restrict__ emb,
        const float* __restrict__ W, const float* __restrict__ Wb,
        const float* __restrict__ Wg, const float* __restrict__ Wg_b) {
    extern __shared__ float e_s[];             // [96][272]
    __shared__ float g_sh[TAILF], w_sh[TAILF];
    __shared__ int s_x[TAILF];
    __shared__ int s_t0;

    int dh = blockIdx.x, b = blockIdx.y, tid = threadIdx.x;
    int lane = tid & 31, w = tid >> 5;
    int kq = lane & 3;
    int dg = dh * 128 + w * 8 + (lane >> 2);

    unsigned long long wp[32];
    const ulonglong2* W2 = (const ulonglong2*)(W + (size_t)dg * DIM + kq * 64);
#pragma unroll
    for (int i = 0; i < 16; i++) {
        ulonglong2 v = W2[i];
        wp[2 * i] = v.x; wp[2 * i + 1] = v.y;
    }
    float wb = Wb[dg];
    float gb = Wg_b[0];
    float4 wg0 = ((const float4*)Wg)[lane * 2];
    float4 wg1 = ((const float4*)Wg)[lane * 2 + 1];

    if (tid < TAILF) s_x[tid] = x[b * TT + (TT - TAILF) + tid];
    __syncthreads();

#pragma unroll
    for (int it = 0; it < 12; it++) {
        int idx4 = it * 512 + tid;
        int r = idx4 >> 6, c4 = idx4 & 63;
        float4 v = *(const float4*)&emb[(size_t)s_x[r] * DIM + c4 * 4];
        *(float4*)&e_s[r * ROWS + (c4 >> 4) * RQP + (c4 & 15) * 4] = v;
    }
    __syncthreads();

#pragma unroll
    for (int j = 0; j < 6; j++) {
        int r = w * 6 + j;
        const float* row = &e_s[r * ROWS + (lane >> 3) * RQP + ((lane * 8) & 63)];
        float4 a0 = *(const float4*)row;
        float4 a1 = *(const float4*)(row + 4);
        float z = a0.x * wg0.x + a0.y * wg0.y + a0.z * wg0.z + a0.w * wg0.w
                + a1.x * wg1.x + a1.y * wg1.y + a1.z * wg1.z + a1.w * wg1.w;
#pragma unroll
        for (int off = 16; off; off >>= 1)
            z += __shfl_xor_sync(0xffffffffu, z, off);
        if (lane == 0) g_sh[r] = 1.f / (1.f + expf(-(z + gb)));
    }
    __syncthreads();

    if (tid < 32) {
        int l = tid;
        float P = g_sh[l * 3] * g_sh[l * 3 + 1] * g_sh[l * 3 + 2];
        float S = P;
#pragma unroll
        for (int off = 1; off < 32; off <<= 1) {
            float v = __shfl_down_sync(0xffffffffu, S, off);
            if (l + off < 32) S *= v;
        }
        float Q = __shfl_down_sync(0xffffffffu, S, 1);
        if (l == 31) Q = 1.f;
        float Sc = Q;
        int myt0 = TT;
#pragma unroll
        for (int j = 2; j >= 0; j--) {
            int slot = l * 3 + j;
            float g = g_sh[slot];
            w_sh[slot] = (1.f - g) * Sc;
            if (Sc >= EPS_CUT) myt0 = (TT - TAILF) + slot;
            Sc *= g;
        }
#pragma unroll
        for (int off = 16; off; off >>= 1) {
            int v = __shfl_xor_sync(0xffffffffu, myt0, off);
            myt0 = v < myt0 ? v : myt0;
        }
        if (l == 0) s_t0 = (myt0 == TT) ? (TT - TAILF) : myt0;
    }
    __syncthreads();

    int t0 = s_t0;
    float acc0 = 0.f, acc1 = 0.f;
    int t = TT - 1;
    for (; t > t0; t -= 2) {
        int sA = t - (TT - TAILF);
        RNN_STEP(sA, acc0);
        RNN_STEP(sA - 1, acc1);
    }
    if (t == t0) RNN_STEP(t - (TT - TAILF), acc0);
    float acc = acc0 + acc1;

    if ((lane & 3) == 0) d_hT[b * DIM + dg] = acc;
}

// ---------------------------------------------------------------------------
// K2: out[b][v] = hT[b,:].head_w[v,:] + head_b[v]  (packed f32x2).
// 125 CTAs x 512 thr. Warp tile 128 v x 8 b; thread tile 4 v x 8 b.
// hT PRE-DUPLICATED in smem as (t,t) 8B pairs -> per kk: 1 swizzled
// LDS.128 (hw granule) + 4 uniform broadcast LDS.128 (8 b-pairs) + 16
// FFMA2. No dup movs on the issue stream.
// ---------------------------------------------------------------------------
#define HS2 66                       // hTd stride (ulonglong), 16B-aligned
#define WSS 260                      // hws row stride (floats) = 1040B
#define SMEM_HEAD (DIM * HS2 * 8 + 2 * 16 * WSS * 4)

__device__ __forceinline__ int swg(int j) { return j ^ ((j >> 3) & 7); }

__global__ void __launch_bounds__(512, 1) k_head(
        const float* __restrict__ hw, const float* __restrict__ hb,
        float* __restrict__ out) {
    extern __shared__ float sm[];
    unsigned long long* hTd = (unsigned long long*)sm;   // [256][HS2]
    float* hws0 = sm + DIM * HS2 * 2;                    // [16][WSS]
    float* hws1 = hws0 + 16 * WSS;

    int tid = threadIdx.x;
    int w = tid >> 5, lane = tid & 31;
    int wv = w & 1, wb = w >> 1;
    int vbase = blockIdx.x * 256;
    int b0 = wb * 8;                   // pair index (8 pairs = 8 b)
    int v0l = wv * 128 + lane * 4;
    int p = swg(wv * 32 + lane) * 4;   // swizzled float offset of lane's granule

    // hTd[k][b] = (hT,hT) (coalesced LDG, one-time)
#pragma unroll
    for (int it = 0; it < 32; it++) {
        int idx = it * 512 + tid;
        int bb = idx >> 8, k = idx & 255;
        hTd[k * HS2 + bb] = dup2(d_hT[bb * DIM + k]);
    }
    // stage hw chunk 0 (swizzled)
#pragma unroll
    for (int r = 0; r < 8; r++) {
        int idx = r * 512 + tid;
        int vl = idx >> 4, kk = idx & 15;
        hws0[kk * WSS + swg(vl >> 2) * 4 + (vl & 3)] =
            hw[(size_t)(vbase + vl) * DIM + kk];
    }
    __syncthreads();

    unsigned long long acc[2][8];
#pragma unroll
    for (int vp = 0; vp < 2; vp++)
#pragma unroll
        for (int bi = 0; bi < 8; bi++) acc[vp][bi] = 0ull;

    for (int ch = 0; ch < 16; ch++) {
        int kb = ch * 16;
        float pf[8];
        if (ch < 15) {
#pragma unroll
            for (int r = 0; r < 8; r++) {
                int idx = r * 512 + tid;
                int vl = idx >> 4, kk = idx & 15;
                pf[r] = hw[(size_t)(vbase + vl) * DIM + kb + 16 + kk];
            }
        }
        const float* buf = (ch & 1) ? hws1 : hws0;
#pragma unroll
        for (int kk = 0; kk < 16; kk++) {
            ulonglong2 h01 = *(const ulonglong2*)(buf + kk * WSS + p);
            const unsigned long long* hrow = &hTd[(kb + kk) * HS2 + b0];
            ulonglong2 q0 = *(const ulonglong2*)(hrow);
            ulonglong2 q1 = *(const ulonglong2*)(hrow + 2);
            ulonglong2 q2 = *(const ulonglong2*)(hrow + 4);
            ulonglong2 q3 = *(const ulonglong2*)(hrow + 6);
            unsigned long long td[8] = {q0.x, q0.y, q1.x, q1.y,
                                        q2.x, q2.y, q3.x, q3.y};
#pragma unroll
            for (int bi = 0; bi < 8; bi++) {
                FMA2(acc[0][bi], h01.x, td[bi]);
                FMA2(acc[1][bi], h01.y, td[bi]);
            }
        }
        if (ch < 15) {
            __syncthreads();
            float* dst = (ch & 1) ? hws0 : hws1;
#pragma unroll
            for (int r = 0; r < 8; r++) {
                int idx = r * 512 + tid;
                int vl = idx >> 4, kk = idx & 15;
                dst[kk * WSS + swg(vl >> 2) * 4 + (vl & 3)] = pf[r];
            }
            __syncthreads();
        }
    }

    // epilogue: float2 stores (v-pairs contiguous), add bias
#pragma unroll
    for (int vp = 0; vp < 2; vp++) {
        int v = vbase + v0l + vp * 2;
        float2 bias = *(const float2*)&hb[v];
#pragma unroll
        for (int bi = 0; bi < 8; bi++) {
            float2 r = unpack2(acc[vp][bi]);
            r.x += bias.x; r.y += bias.y;
            *(float2*)&out[(size_t)(b0 + bi) * VOCAB + v] = r;
        }
    }
}

// ---------------------------------------------------------------------------
extern "C" void kernel_launch(void* const* d_in, const int* in_sizes, int n_in,
                              void* d_out, int out_size) {
    const int*   x      = (const int*)d_in[0];
    const float* emb    = (const float*)d_in[1];
    const float* W_w    = (const float*)d_in[2];
    const float* W_b    = (const float*)d_in[3];
    const float* Wg_w   = (const float*)d_in[4];
    const float* Wg_b   = (const float*)d_in[5];
    const float* head_w = (const float*)d_in[6];
    const float* head_b = (const float*)d_in[7];
    float* out = (float*)d_out;

    cudaFuncSetAttribute(k_fused, cudaFuncAttributeMaxDynamicSharedMemorySize,
                         DSMEM_F);
    k_fused<<<dim3(2, BB), 512, DSMEM_F>>>(x, emb, W_w, W_b, Wg_w, Wg_b);
    cudaFuncSetAttribute(k_head, cudaFuncAttributeMaxDynamicSharedMemorySize,
                         SMEM_HEAD);
    k_head<<<VOCAB / 256, 512, SMEM_HEAD>>>(head_w, head_b, out);
}

// round 17
// speedup vs baseline: 1.7099x; 1.7099x over previous
#include <cuda_runtime.h>
#include <cuda_bf16.h>
#include <math.h>
#include <stdint.h>

#define BB 64
#define TT 2048
#define DIM 256
#define VOCAB 32000
#define TAILF 96
#define EPS_CUT 1e-7f

// hT as bf16 hi/lo, [b][k] row-major, packed 8 bf16 per uint4 (16B aligned)
__device__ uint4 d_hThi4[BB * DIM / 8];
__device__ uint4 d_hTlo4[BB * DIM / 8];

// packed f32x2 FMA: c = a*b + c
#define FMA2(c, a, b) \
    asm("fma.rn.f32x2 %0, %1, %2, %0;" : "+l"(c) : "l"(a), "l"(b))
__device__ __forceinline__ float2 unpack2(unsigned long long v) {
    float2 r;
    asm("mov.b64 {%0,%1}, %2;" : "=f"(r.x), "=f"(r.y) : "l"(v));
    return r;
}

// ---------------------------------------------------------------------------
// K1 (fused scan+main) — R13's measured-good version; only the final write
// changes: packs bf16 hi/lo pairs into d_hThi4/d_hTlo4.
// ---------------------------------------------------------------------------
#define RQP 68
#define ROWS 272
#define DSMEM_F (TAILF * ROWS * 4)

__global__ void __launch_bounds__(512, 1) k_fused(
        const int* __restrict__ x, const float* __restrict__ emb,
        const float* __restrict__ W, const float* __restrict__ Wb,
        const float* __restrict__ Wg, const float* __restrict__ Wg_b) {
    extern __shared__ float e_s[];             // [96][272]
    __shared__ float g_sh[TAILF], w_sh[TAILF];
    __shared__ int s_x[TAILF];
    __shared__ int s_t0;

    int dh = blockIdx.x, b = blockIdx.y, tid = threadIdx.x;
    int lane = tid & 31, w = tid >> 5;
    int kq = lane & 3;
    int dg = dh * 128 + w * 8 + (lane >> 2);

    unsigned long long wp[32];
    const ulonglong2* W2 = (const ulonglong2*)(W + (size_t)dg * DIM + kq * 64);
#pragma unroll
    for (int i = 0; i < 16; i++) {
        ulonglong2 v = W2[i];
        wp[2 * i] = v.x; wp[2 * i + 1] = v.y;
    }
    float wb = Wb[dg];
    float gb = Wg_b[0];
    float4 wg0 = ((const float4*)Wg)[lane * 2];
    float4 wg1 = ((const float4*)Wg)[lane * 2 + 1];

    if (tid < TAILF) s_x[tid] = x[b * TT + (TT - TAILF) + tid];
    __syncthreads();

#pragma unroll
    for (int it = 0; it < 12; it++) {
        int idx4 = it * 512 + tid;
        int r = idx4 >> 6, c4 = idx4 & 63;
        float4 v = *(const float4*)&emb[(size_t)s_x[r] * DIM + c4 * 4];
        *(float4*)&e_s[r * ROWS + (c4 >> 4) * RQP + (c4 & 15) * 4] = v;
    }
    __syncthreads();

#pragma unroll
    for (int j = 0; j < 6; j++) {
        int r = w * 6 + j;
        const float* row = &e_s[r * ROWS + (lane >> 3) * RQP + ((lane * 8) & 63)];
        float4 a0 = *(const float4*)row;
        float4 a1 = *(const float4*)(row + 4);
        float z = a0.x * wg0.x + a0.y * wg0.y + a0.z * wg0.z + a0.w * wg0.w
                + a1.x * wg1.x + a1.y * wg1.y + a1.z * wg1.z + a1.w * wg1.w;
#pragma unroll
        for (int off = 16; off; off >>= 1)
            z += __shfl_xor_sync(0xffffffffu, z, off);
        if (lane == 0) g_sh[r] = 1.f / (1.f + expf(-(z + gb)));
    }
    __syncthreads();

    if (tid < 32) {
        int l = tid;
        float P = g_sh[l * 3] * g_sh[l * 3 + 1] * g_sh[l * 3 + 2];
        float S = P;
#pragma unroll
        for (int off = 1; off < 32; off <<= 1) {
            float v = __shfl_down_sync(0xffffffffu, S, off);
            if (l + off < 32) S *= v;
        }
        float Q = __shfl_down_sync(0xffffffffu, S, 1);
        if (l == 31) Q = 1.f;
        float Sc = Q;
        int myt0 = TT;
#pragma unroll
        for (int j = 2; j >= 0; j--) {
            int slot = l * 3 + j;
            float g = g_sh[slot];
            w_sh[slot] = (1.f - g) * Sc;
            if (Sc >= EPS_CUT) myt0 = (TT - TAILF) + slot;
            Sc *= g;
        }
#pragma unroll
        for (int off = 16; off; off >>= 1) {
            int v = __shfl_xor_sync(0xffffffffu, myt0, off);
            myt0 = v < myt0 ? v : myt0;
        }
        if (l == 0) s_t0 = (myt0 == TT) ? (TT - TAILF) : myt0;
    }
    __syncthreads();

    int t0 = s_t0;
    float acc = 0.f;
    for (int t = TT - 1; t >= t0; t--) {
        int slot = t - (TT - TAILF);
        const ulonglong2* ev = (const ulonglong2*)&e_s[slot * ROWS + kq * RQP];
        unsigned long long a0 = 0, a1 = 0, a2 = 0, a3 = 0;
#pragma unroll
        for (int j = 0; j < 16; j += 2) {
            ulonglong2 e0 = ev[j];
            FMA2(a0, wp[2 * j], e0.x);
            FMA2(a1, wp[2 * j + 1], e0.y);
            ulonglong2 e1 = ev[j + 1];
            FMA2(a2, wp[2 * j + 2], e1.x);
            FMA2(a3, wp[2 * j + 3], e1.y);
        }
        float2 f0 = unpack2(a0), f1 = unpack2(a1);
        float2 f2 = unpack2(a2), f3 = unpack2(a3);
        float ps = ((f0.x + f0.y) + (f1.x + f1.y)) +
                   ((f2.x + f2.y) + (f3.x + f3.y));
        ps += __shfl_xor_sync(0xffffffffu, ps, 1);
        ps += __shfl_xor_sync(0xffffffffu, ps, 2);
        acc = fmaf(w_sh[slot], tanhf(ps + wb), acc);
    }

    // pack bf16 hi/lo pairs: lane L (L&3==0) holds dg; partner at L+4 = dg+1
    __nv_bfloat16 hi = __float2bfloat16_rn(acc);
    float lof = acc - __bfloat162float(hi);
    __nv_bfloat16 lo = __float2bfloat16_rn(lof);
    unsigned hbits = (unsigned)__bfloat16_as_ushort(hi);
    unsigned lbits = (unsigned)__bfloat16_as_ushort(lo);
    unsigned hup = __shfl_down_sync(0xffffffffu, hbits, 4);
    unsigned lup = __shfl_down_sync(0xffffffffu, lbits, 4);
    if ((lane & 7) == 0) {
        int pi = (b * DIM + dg) >> 1;
        ((unsigned*)d_hThi4)[pi] = hbits | (hup << 16);
        ((unsigned*)d_hTlo4)[pi] = lbits | (lup << 16);
    }
}

// ---------------------------------------------------------------------------
// K2: out = hT @ head_w^T + head_b via bf16-split mma.sync (CLEAN version).
//   out = Ahi*Bhi + Ahi*Blo + Alo*Bhi  (fp32 accum; lo*lo dropped ~2^-16)
// A (hT hi/lo) staged in PADDED smem (row stride 132 uints = 528B ->
// conflict-free frag LDS.32); B (head_w) direct LDG fp32 -> in-register
// bf16 split (R2-verified fragment mapping). ZERO barriers in the k-loop.
// 125 CTAs x 256 thr; block tile M=64(all b) x N=256 v; warp 64x32;
// per warp per kc: 8 LDG + 32 LDS + cvts + 48 HMMA.
// ---------------------------------------------------------------------------
#define AROW 132                      // uints per padded hT row
#define ASMEM (2 * 64 * AROW * 4)     // 67584 B

__device__ __forceinline__ void mma_bf16(float* d, const unsigned* a,
                                         const unsigned* b) {
    asm volatile(
        "mma.sync.aligned.m16n8k16.row.col.f32.bf16.bf16.f32 "
        "{%0,%1,%2,%3},{%4,%5,%6,%7},{%8,%9},{%0,%1,%2,%3};\n"
        : "+f"(d[0]), "+f"(d[1]), "+f"(d[2]), "+f"(d[3])
        : "r"(a[0]), "r"(a[1]), "r"(a[2]), "r"(a[3]), "r"(b[0]), "r"(b[1]));
}

__global__ void __launch_bounds__(256, 1) k_head_mma(
        const float* __restrict__ hw, const float* __restrict__ hb,
        float* __restrict__ out) {
    extern __shared__ unsigned asm_s[];
    unsigned* Ah_s = asm_s;            // [64][AROW]
    unsigned* Al_s = asm_s + 64 * AROW;

    int tid = threadIdx.x;
    int w = tid >> 5, lane = tid & 31;
    int g = lane >> 2, tig = lane & 3;
    int vbase = blockIdx.x * 256;

    // stage hT hi/lo into padded smem (uint4 = 8 bf16 = 8 k of one row)
#pragma unroll
    for (int it = 0; it < 8; it++) {
        int i = it * 256 + tid;            // 2048 uint4
        int r = i >> 5, c16 = i & 31;
        *(uint4*)&Ah_s[r * AROW + c16 * 4] = d_hThi4[i];
        *(uint4*)&Al_s[r * AROW + c16 * 4] = d_hTlo4[i];
    }
    __syncthreads();

    float acc[4][4][4];
#pragma unroll
    for (int mt = 0; mt < 4; mt++)
#pragma unroll
        for (int nt = 0; nt < 4; nt++)
#pragma unroll
            for (int r = 0; r < 4; r++) acc[mt][nt][r] = 0.f;

    for (int kc = 0; kc < 16; kc++) {
        // ---- B fragments: direct global fp32, split in registers ----
        unsigned bh[4][2], bl[4][2];
#pragma unroll
        for (int nt = 0; nt < 4; nt++) {
            int v = vbase + w * 32 + nt * 8 + g;
            const float* r = hw + (size_t)v * DIM + kc * 16 + 2 * tig;
            float2 f0 = *(const float2*)r;
            float2 f1 = *(const float2*)(r + 8);
            __nv_bfloat162 h0 = __float22bfloat162_rn(f0);
            float2 r0 = make_float2(f0.x - __bfloat162float(h0.x),
                                    f0.y - __bfloat162float(h0.y));
            __nv_bfloat162 l0 = __float22bfloat162_rn(r0);
            __nv_bfloat162 h1 = __float22bfloat162_rn(f1);
            float2 r1 = make_float2(f1.x - __bfloat162float(h1.x),
                                    f1.y - __bfloat162float(h1.y));
            __nv_bfloat162 l1 = __float22bfloat162_rn(r1);
            bh[nt][0] = *(unsigned*)&h0; bh[nt][1] = *(unsigned*)&h1;
            bl[nt][0] = *(unsigned*)&l0; bl[nt][1] = *(unsigned*)&l1;
        }
        // ---- A fragments: conflict-free LDS.32 from padded smem ----
        unsigned ahi[4][4], alo[4][4];
#pragma unroll
        for (int mt = 0; mt < 4; mt++) {
            int r0 = (mt * 16 + g) * AROW + kc * 8 + tig;
            int r1 = (mt * 16 + g + 8) * AROW + kc * 8 + tig;
            ahi[mt][0] = Ah_s[r0];     ahi[mt][1] = Ah_s[r1];
            ahi[mt][2] = Ah_s[r0 + 4]; ahi[mt][3] = Ah_s[r1 + 4];
            alo[mt][0] = Al_s[r0];     alo[mt][1] = Al_s[r1];
            alo[mt][2] = Al_s[r0 + 4]; alo[mt][3] = Al_s[r1 + 4];
        }
#pragma unroll
        for (int nt = 0; nt < 4; nt++)
#pragma unroll
            for (int mt = 0; mt < 4; mt++) {
                mma_bf16(acc[mt][nt], ahi[mt], bh[nt]);
                mma_bf16(acc[mt][nt], ahi[mt], bl[nt]);
                mma_bf16(acc[mt][nt], alo[mt], bh[nt]);
            }
    }

    // epilogue: add bias, write out [b][VOCAB]
#pragma unroll
    for (int nt = 0; nt < 4; nt++) {
        int v = vbase + w * 32 + nt * 8 + tig * 2;
        float2 bias = *(const float2*)&hb[v];
#pragma unroll
        for (int mt = 0; mt < 4; mt++) {
            int b0r = mt * 16 + g;
            float2 o0, o1;
            o0.x = acc[mt][nt][0] + bias.x;
            o0.y = acc[mt][nt][1] + bias.y;
            o1.x = acc[mt][nt][2] + bias.x;
            o1.y = acc[mt][nt][3] + bias.y;
            *(float2*)&out[(size_t)b0r * VOCAB + v] = o0;
            *(float2*)&out[(size_t)(b0r + 8) * VOCAB + v] = o1;
        }
    }
}

// ---------------------------------------------------------------------------
extern "C" void kernel_launch(void* const* d_in, const int* in_sizes, int n_in,
                              void* d_out, int out_size) {
    const int*   x      = (const int*)d_in[0];
    const float* emb    = (const float*)d_in[1];
    const float* W_w    = (const float*)d_in[2];
    const float* W_b    = (const float*)d_in[3];
    const float* Wg_w   = (const float*)d_in[4];
    const float* Wg_b   = (const float*)d_in[5];
    const float* head_w = (const float*)d_in[6];
    const float* head_b = (const float*)d_in[7];
    float* out = (float*)d_out;

    cudaFuncSetAttribute(k_fused, cudaFuncAttributeMaxDynamicSharedMemorySize,
                         DSMEM_F);
    k_fused<<<dim3(2, BB), 512, DSMEM_F>>>(x, emb, W_w, W_b, Wg_w, Wg_b);
    cudaFuncSetAttribute(k_head_mma,
                         cudaFuncAttributeMaxDynamicSharedMemorySize, ASMEM);
    k_head_mma<<<VOCAB / 256, 256, ASMEM>>>(head_w, head_b, out);
}